// round 7
// baseline (speedup 1.0000x reference)
#include <cuda_runtime.h>
#include <cstdint>

#define N_V    12288
#define D_F    32
#define N_E    196608
#define THR    256
#define RPT    4                  // rows per thread
#define RB     (THR * RPT)        // 1024 rows per block
#define NBR    (N_V / RB)         // 12
#define SPLIT  24
#define JSEG   (N_V / SPLIT)      // 512
#define SCALE  20.0f
#define INV_S2 (1.0f / (SCALE * SCALE))
#define EPSF   1e-12f
#define BIGI   0x7FFFFFFF

__device__ uint32_t g_qx[N_V * 8];    // int8-packed rows (8 x u32 per row)
__device__ int      g_isq[N_V];       // integer squared norms
__device__ float    g_v[N_V];
__device__ int      g_part[N_V * SPLIT * 6];

__device__ __forceinline__ void ins6i(int (&m)[6], int d) {
    if (d < m[5]) {
        int c4 = max(m[4], d);
        int c3 = max(m[3], d);
        int c2 = max(m[2], d);
        int c1 = max(m[1], d);
        int c0 = max(m[0], d);
        m[5] = min(m[5], c4);
        m[4] = min(m[4], c3);
        m[3] = min(m[3], c2);
        m[2] = min(m[2], c1);
        m[1] = min(m[1], c0);
        m[0] = min(m[0], d);
    }
}

// ---------------------------------------------------------------------------
// Kernel 1: quantize x -> int8 (scale 20), integer squared norms via dp4a
// ---------------------------------------------------------------------------
__global__ void conv_kernel(const float* __restrict__ x) {
    int i = blockIdx.x * blockDim.x + threadIdx.x;
    if (i < N_V) {
        const float4* xr = reinterpret_cast<const float4*>(x + (size_t)i * D_F);
        uint32_t pk[8];
        int isq = 0;
        #pragma unroll
        for (int q = 0; q < 8; q++) {
            float4 v = xr[q];
            int q0 = __float2int_rn(fminf(fmaxf(v.x * SCALE, -127.f), 127.f));
            int q1 = __float2int_rn(fminf(fmaxf(v.y * SCALE, -127.f), 127.f));
            int q2 = __float2int_rn(fminf(fmaxf(v.z * SCALE, -127.f), 127.f));
            int q3 = __float2int_rn(fminf(fmaxf(v.w * SCALE, -127.f), 127.f));
            pk[q] = (uint32_t)(q0 & 0xFF) | ((uint32_t)(q1 & 0xFF) << 8) |
                    ((uint32_t)(q2 & 0xFF) << 16) | ((uint32_t)(q3 & 0xFF) << 24);
            isq = __dp4a((int)pk[q], (int)pk[q], isq);
        }
        g_isq[i] = isq;
        uint4* dst = reinterpret_cast<uint4*>(g_qx + (size_t)i * 8);
        dst[0] = make_uint4(pk[0], pk[1], pk[2], pk[3]);
        dst[1] = make_uint4(pk[4], pk[5], pk[6], pk[7]);
    }
}

// ---------------------------------------------------------------------------
// Kernel 2: int8 knn, 4-j unrolled with deferred selection.
// d~2(i,j) tracked in (isq_j - 2*idot) space; isq_i folded at the end.
// 256 threads x 4 rows/thread; whole 512-j split staged in smem once.
// Grid (12, 24) = 288 CTAs = one full wave at occupancy 2.
// ---------------------------------------------------------------------------
__global__ void __launch_bounds__(THR, 2) knn_kernel() {
    __shared__ uint32_t tile[JSEG * 8];   // 16 KB
    __shared__ int      sqt[JSEG];        // 2 KB

    const int t    = threadIdx.x;
    const int base = blockIdx.x * RB;
    const int jb   = blockIdx.y * JSEG;

    // this thread's 4 row vectors (8 packed u32 each)
    uint32_t rq[RPT][8];
    #pragma unroll
    for (int r = 0; r < RPT; r++) {
        const uint4* p =
            reinterpret_cast<const uint4*>(g_qx + (size_t)(base + r * THR + t) * 8);
        uint4 a = p[0], b = p[1];
        rq[r][0] = a.x; rq[r][1] = a.y; rq[r][2] = a.z; rq[r][3] = a.w;
        rq[r][4] = b.x; rq[r][5] = b.y; rq[r][6] = b.z; rq[r][7] = b.w;
    }

    // stage the j tile (coalesced uint4 copy) + integer norms
    {
        const uint4* src = reinterpret_cast<const uint4*>(g_qx + (size_t)jb * 8);
        uint4* dst = reinterpret_cast<uint4*>(tile);
        #pragma unroll
        for (int q = 0; q < (JSEG * 8 / 4) / THR; q++)   // 4 per thread
            dst[t + q * THR] = src[t + q * THR];
        sqt[t]       = g_isq[jb + t];
        sqt[t + THR] = g_isq[jb + THR + t];
    }
    __syncthreads();

    int m[RPT][6];
    #pragma unroll
    for (int r = 0; r < RPT; r++)
        #pragma unroll
        for (int q = 0; q < 6; q++) m[r][q] = BIGI;

    #pragma unroll 1
    for (int j = 0; j < JSEG; j += 4) {
        uint4 va[4], vb[4];
        int   sj[4];
        #pragma unroll
        for (int q = 0; q < 4; q++) {
            va[q] = *reinterpret_cast<const uint4*>(&tile[(j + q) * 8]);
            vb[q] = *reinterpret_cast<const uint4*>(&tile[(j + q) * 8 + 4]);
            sj[q] = sqt[j + q];
        }
        #pragma unroll
        for (int r = 0; r < RPT; r++) {
            int d[4];
            #pragma unroll
            for (int q = 0; q < 4; q++) {
                int acc = __dp4a((int)va[q].x, (int)rq[r][0], 0);
                acc = __dp4a((int)va[q].y, (int)rq[r][1], acc);
                acc = __dp4a((int)va[q].z, (int)rq[r][2], acc);
                acc = __dp4a((int)va[q].w, (int)rq[r][3], acc);
                acc = __dp4a((int)vb[q].x, (int)rq[r][4], acc);
                acc = __dp4a((int)vb[q].y, (int)rq[r][5], acc);
                acc = __dp4a((int)vb[q].z, (int)rq[r][6], acc);
                acc = __dp4a((int)vb[q].w, (int)rq[r][7], acc);
                d[q] = sj[q] - 2 * acc;
            }
            int dmin = min(min(d[0], d[1]), min(d[2], d[3]));
            if (dmin < m[r][5]) {       // rare path (~27 hits / row / split)
                ins6i(m[r], d[0]);
                ins6i(m[r], d[1]);
                ins6i(m[r], d[2]);
                ins6i(m[r], d[3]);
            }
        }
    }

    #pragma unroll
    for (int r = 0; r < RPT; r++) {
        const int row = base + r * THR + t;
        const int isq = g_isq[row];
        int* dst = g_part + (size_t)row * (SPLIT * 6) + blockIdx.y * 6;
        #pragma unroll
        for (int q = 0; q < 6; q++) dst[q] = m[r][q] + isq;
    }
}

// ---------------------------------------------------------------------------
// Kernel 3: merge 24 splits -> vertex filtration value
// v = 1 - sum_{k=1..5} exp(-sqrt(max(d2_k, eps))) / 6   (m[0]=0=self dropped)
// ---------------------------------------------------------------------------
__global__ void finalize_vertex_kernel(float* __restrict__ out) {
    int i = blockIdx.x * blockDim.x + threadIdx.x;
    if (i < N_V) {
        const int* src = g_part + (size_t)i * (SPLIT * 6);
        int m[6] = {BIGI, BIGI, BIGI, BIGI, BIGI, BIGI};
        #pragma unroll 4
        for (int k = 0; k < SPLIT * 6; k++) ins6i(m, src[k]);
        float sum = 0.f;
        #pragma unroll
        for (int q = 1; q < 6; q++) {
            float d2 = (float)m[q] * INV_S2;
            sum += expf(-sqrtf(fmaxf(d2, EPSF)));
        }
        float v = 1.f - sum * (1.f / 6.f);
        g_v[i] = v;
        out[2 * i]     = v;
        out[2 * i + 1] = 0.f;
    }
}

// ---------------------------------------------------------------------------
// Kernel 4: edge filtration with cooperative coalesced gathers.
// Warp = 4 edges; each 8-lane group loads one 128B row coalesced (4 lines
// per warp-LDG vs 32 for the naive gather), partial sums reduced by shfl.
// Reference's per-edge pair sort is a no-op (outputs symmetric in (u,w)).
// ---------------------------------------------------------------------------
__global__ void __launch_bounds__(256) edge_kernel(const float* __restrict__ x,
                                                   const int* __restrict__ ei,
                                                   float* __restrict__ out) {
    const int warp = (blockIdx.x * blockDim.x + threadIdx.x) >> 5;
    const int lane = threadIdx.x & 31;
    const int k    = lane >> 3;     // edge within warp (0..3)
    const int sub  = lane & 7;      // dim-group within row (0..7)
    const int e    = warp * 4 + k;
    if (e < N_E) {
        const int u = ei[e];
        const int w = ei[N_E + e];
        float4 a = *reinterpret_cast<const float4*>(x + (size_t)u * D_F + sub * 4);
        float4 b = *reinterpret_cast<const float4*>(x + (size_t)w * D_F + sub * 4);
        float dx = a.x - b.x, dy = a.y - b.y;
        float dz = a.z - b.z, dw = a.w - b.w;
        float s = dx * dx + dy * dy + dz * dz + dw * dw;
        s += __shfl_xor_sync(0xFFFFFFFFu, s, 1);
        s += __shfl_xor_sync(0xFFFFFFFFu, s, 2);
        s += __shfl_xor_sync(0xFFFFFFFFu, s, 4);
        if (sub == 0) {
            float n  = sqrtf(fmaxf(s, EPSF));
            float ev = fmaxf(g_v[u], g_v[w]);
            *reinterpret_cast<float2*>(out + 2 * (N_V + e)) =
                make_float2(ev, 1.f - expf(-n));
        }
    }
}

// ---------------------------------------------------------------------------
extern "C" void kernel_launch(void* const* d_in, const int* in_sizes, int n_in,
                              void* d_out, int out_size) {
    (void)in_sizes; (void)n_in; (void)out_size;
    const float* x   = (const float*)d_in[0];
    const int*   ei  = (const int*)d_in[1];
    float*       out = (float*)d_out;

    conv_kernel<<<(N_V + 255) / 256, 256>>>(x);

    dim3 grid(NBR, SPLIT);
    knn_kernel<<<grid, THR>>>();

    finalize_vertex_kernel<<<(N_V + 255) / 256, 256>>>(out);
    // 4 edges per warp -> N_E/4 warps -> /8 warps per block
    edge_kernel<<<(N_E / 4 + 7) / 8, 256>>>(x, ei, out);
}

// round 8
// speedup vs baseline: 1.0220x; 1.0220x over previous
#include <cuda_runtime.h>
#include <cstdint>

#define N_V    12288
#define D_F    32
#define N_E    196608
#define NSPLIT 2
#define JSEG   (N_V / NSPLIT)     // 6144
#define TJ     512                // j rows staged per tile
#define NTILE  (JSEG / TJ)        // 12
#define IPC    64                 // i rows per CTA (4 warps x 16)
#define NIB    (N_V / IPC)        // 192
#define SCALE  20.0f
#define INV_S2 (1.0f / (SCALE * SCALE))
#define EPSF   1e-12f
#define BIGI   0x7FFFFFFF

__device__ uint32_t g_qx[N_V * 8];    // int8-packed rows (8 x u32 per row)
__device__ int      g_isq[N_V];       // integer squared norms
__device__ float    g_v[N_V];
__device__ int      g_part[N_V * NSPLIT * 6];

__device__ __forceinline__ void ins6i(int (&m)[6], int d) {
    if (d < m[5]) {
        int c4 = max(m[4], d);
        int c3 = max(m[3], d);
        int c2 = max(m[2], d);
        int c1 = max(m[1], d);
        int c0 = max(m[0], d);
        m[5] = min(m[5], c4);
        m[4] = min(m[4], c3);
        m[3] = min(m[3], c2);
        m[2] = min(m[2], c1);
        m[1] = min(m[1], c0);
        m[0] = min(m[0], d);
    }
}

// ---------------------------------------------------------------------------
// Kernel 1: quantize x -> int8 (scale 20), integer squared norms via dp4a
// ---------------------------------------------------------------------------
__global__ void conv_kernel(const float* __restrict__ x) {
    int i = blockIdx.x * blockDim.x + threadIdx.x;
    if (i < N_V) {
        const float4* xr = reinterpret_cast<const float4*>(x + (size_t)i * D_F);
        uint32_t pk[8];
        int isq = 0;
        #pragma unroll
        for (int q = 0; q < 8; q++) {
            float4 v = xr[q];
            int q0 = __float2int_rn(fminf(fmaxf(v.x * SCALE, -127.f), 127.f));
            int q1 = __float2int_rn(fminf(fmaxf(v.y * SCALE, -127.f), 127.f));
            int q2 = __float2int_rn(fminf(fmaxf(v.z * SCALE, -127.f), 127.f));
            int q3 = __float2int_rn(fminf(fmaxf(v.w * SCALE, -127.f), 127.f));
            pk[q] = (uint32_t)(q0 & 0xFF) | ((uint32_t)(q1 & 0xFF) << 8) |
                    ((uint32_t)(q2 & 0xFF) << 16) | ((uint32_t)(q3 & 0xFF) << 24);
            isq = __dp4a((int)pk[q], (int)pk[q], isq);
        }
        g_isq[i] = isq;
        uint4* dst = reinterpret_cast<uint4*>(g_qx + (size_t)i * 8);
        dst[0] = make_uint4(pk[0], pk[1], pk[2], pk[3]);
        dst[1] = make_uint4(pk[4], pk[5], pk[6], pk[7]);
    }
}

// ---------------------------------------------------------------------------
// Kernel 2: int8 knn via warp mma.sync m16n8k32 (legacy IMMA tensor path).
// One mma = full 16i x 8j dot tile (D=32=k32). A fragment register-resident
// for the whole kernel. d~2 tracked in (isq_j - 2*dot) space (exact int),
// isq_i folded at the end. Per-lane top-6 for rows g and g+8, merged across
// the 4 lanes of a quad via snapshotted shfl tournament.
// Grid (192, 2): 384 CTAs x 128 thr, whole grid resident in one wave.
// ---------------------------------------------------------------------------
__global__ void __launch_bounds__(128, 3) knn_kernel() {
    __shared__ uint32_t tile[TJ * 8];   // 16 KB
    __shared__ int      sqt[TJ];        // 2 KB

    const int t    = threadIdx.x;
    const int w    = t >> 5;
    const int lane = t & 31;
    const int g    = lane >> 2;         // row group 0..7
    const int th   = lane & 3;          // thread-in-quad
    const int ibase = blockIdx.x * IPC + w * 16;
    const int jb0   = blockIdx.y * JSEG;

    // A fragment: rows ibase+g (a0,a2) and ibase+g+8 (a1,a3), k-halves
    const uint32_t a0 = g_qx[(size_t)(ibase + g) * 8 + th];
    const uint32_t a1 = g_qx[(size_t)(ibase + g + 8) * 8 + th];
    const uint32_t a2 = g_qx[(size_t)(ibase + g) * 8 + th + 4];
    const uint32_t a3 = g_qx[(size_t)(ibase + g + 8) * 8 + th + 4];

    int mA[6] = {BIGI, BIGI, BIGI, BIGI, BIGI, BIGI};
    int mB[6] = {BIGI, BIGI, BIGI, BIGI, BIGI, BIGI};
    const int z = 0;

    for (int tl = 0; tl < NTILE; tl++) {
        __syncthreads();
        const int jb = jb0 + tl * TJ;
        {   // stage TJ j-rows (coalesced uint4) + norms
            const uint4* src = reinterpret_cast<const uint4*>(g_qx + (size_t)jb * 8);
            uint4* dst = reinterpret_cast<uint4*>(tile);
            #pragma unroll
            for (int q = 0; q < (TJ * 8 / 4) / 128; q++)   // 8 per thread
                dst[t + q * 128] = src[t + q * 128];
            #pragma unroll
            for (int q = 0; q < TJ / 128; q++)
                sqt[t + q * 128] = g_isq[jb + t + q * 128];
        }
        __syncthreads();

        #pragma unroll 2
        for (int jg = 0; jg < TJ / 8; jg++) {
            // B fragment: col n = g, k-halves at th*4 bytes
            const uint32_t b0 = tile[(jg * 8 + g) * 8 + th];
            const uint32_t b1 = tile[(jg * 8 + g) * 8 + th + 4];
            // norms for this lane's two accumulator columns (th*2, th*2+1)
            const int2 sj = *reinterpret_cast<const int2*>(&sqt[jg * 8 + th * 2]);
            int c0, c1, c2, c3;
            asm volatile(
                "mma.sync.aligned.m16n8k32.row.col.s32.s8.s8.s32 "
                "{%0,%1,%2,%3}, {%4,%5,%6,%7}, {%8,%9}, {%10,%11,%12,%13};"
                : "=r"(c0), "=r"(c1), "=r"(c2), "=r"(c3)
                : "r"(a0), "r"(a1), "r"(a2), "r"(a3), "r"(b0), "r"(b1),
                  "r"(z), "r"(z), "r"(z), "r"(z));
            const int d0 = sj.x - 2 * c0;   // row g,   col th*2
            const int d1 = sj.y - 2 * c1;   // row g,   col th*2+1
            const int d2 = sj.x - 2 * c2;   // row g+8, col th*2
            const int d3 = sj.y - 2 * c3;   // row g+8, col th*2+1
            if (min(d0, d1) < mA[5]) { ins6i(mA, d0); ins6i(mA, d1); }
            if (min(d2, d3) < mB[5]) { ins6i(mB, d2); ins6i(mB, d3); }
        }
    }

    // tournament merge across the 4 lanes of each quad (snapshot then insert)
    #pragma unroll
    for (int mask = 1; mask <= 2; mask <<= 1) {
        int tA[6], tB[6];
        #pragma unroll
        for (int q = 0; q < 6; q++) { tA[q] = mA[q]; tB[q] = mB[q]; }
        #pragma unroll
        for (int q = 0; q < 6; q++) {
            ins6i(mA, __shfl_xor_sync(0xFFFFFFFFu, tA[q], mask));
            ins6i(mB, __shfl_xor_sync(0xFFFFFFFFu, tB[q], mask));
        }
    }

    if (th == 0) {
        const int rA = ibase + g;
        const int rB = ibase + g + 8;
        const int isqA = g_isq[rA];
        const int isqB = g_isq[rB];
        int* dA = g_part + (size_t)rA * (NSPLIT * 6) + blockIdx.y * 6;
        int* dB = g_part + (size_t)rB * (NSPLIT * 6) + blockIdx.y * 6;
        #pragma unroll
        for (int q = 0; q < 6; q++) { dA[q] = mA[q] + isqA; dB[q] = mB[q] + isqB; }
    }
}

// ---------------------------------------------------------------------------
// Kernel 3: merge 2 splits -> vertex filtration value
// v = 1 - sum_{k=1..5} exp(-sqrt(max(d2_k, eps))) / 6   (m[0]=0=self dropped)
// ---------------------------------------------------------------------------
__global__ void finalize_vertex_kernel(float* __restrict__ out) {
    int i = blockIdx.x * blockDim.x + threadIdx.x;
    if (i < N_V) {
        const int* src = g_part + (size_t)i * (NSPLIT * 6);
        int m[6] = {BIGI, BIGI, BIGI, BIGI, BIGI, BIGI};
        #pragma unroll
        for (int k = 0; k < NSPLIT * 6; k++) ins6i(m, src[k]);
        float sum = 0.f;
        #pragma unroll
        for (int q = 1; q < 6; q++) {
            float d2 = (float)m[q] * INV_S2;
            sum += expf(-sqrtf(fmaxf(d2, EPSF)));
        }
        float v = 1.f - sum * (1.f / 6.f);
        g_v[i] = v;
        out[2 * i]     = v;
        out[2 * i + 1] = 0.f;
    }
}

// ---------------------------------------------------------------------------
// Kernel 4: edge filtration with cooperative coalesced gathers.
// Warp = 4 edges; each 8-lane group loads one 128B row coalesced, partial
// sums reduced by shfl. Reference's per-edge pair sort is a no-op here.
// ---------------------------------------------------------------------------
__global__ void __launch_bounds__(256) edge_kernel(const float* __restrict__ x,
                                                   const int* __restrict__ ei,
                                                   float* __restrict__ out) {
    const int warp = (blockIdx.x * blockDim.x + threadIdx.x) >> 5;
    const int lane = threadIdx.x & 31;
    const int k    = lane >> 3;
    const int sub  = lane & 7;
    const int e    = warp * 4 + k;
    if (e < N_E) {
        const int u = ei[e];
        const int w = ei[N_E + e];
        float4 a = *reinterpret_cast<const float4*>(x + (size_t)u * D_F + sub * 4);
        float4 b = *reinterpret_cast<const float4*>(x + (size_t)w * D_F + sub * 4);
        float dx = a.x - b.x, dy = a.y - b.y;
        float dz = a.z - b.z, dw = a.w - b.w;
        float s = dx * dx + dy * dy + dz * dz + dw * dw;
        s += __shfl_xor_sync(0xFFFFFFFFu, s, 1);
        s += __shfl_xor_sync(0xFFFFFFFFu, s, 2);
        s += __shfl_xor_sync(0xFFFFFFFFu, s, 4);
        if (sub == 0) {
            float n  = sqrtf(fmaxf(s, EPSF));
            float ev = fmaxf(g_v[u], g_v[w]);
            *reinterpret_cast<float2*>(out + 2 * (N_V + e)) =
                make_float2(ev, 1.f - expf(-n));
        }
    }
}

// ---------------------------------------------------------------------------
extern "C" void kernel_launch(void* const* d_in, const int* in_sizes, int n_in,
                              void* d_out, int out_size) {
    (void)in_sizes; (void)n_in; (void)out_size;
    const float* x   = (const float*)d_in[0];
    const int*   ei  = (const int*)d_in[1];
    float*       out = (float*)d_out;

    conv_kernel<<<(N_V + 255) / 256, 256>>>(x);

    dim3 grid(NIB, NSPLIT);
    knn_kernel<<<grid, 128>>>();

    finalize_vertex_kernel<<<(N_V + 255) / 256, 256>>>(out);
    edge_kernel<<<(N_E / 4 + 7) / 8, 256>>>(x, ei, out);
}